// round 4
// baseline (speedup 1.0000x reference)
#include <cuda_runtime.h>
#include <cstdint>
#include <math_constants.h>

#define BATCH 4096
#define VSZ   256
#define NU    129
#define SKIP  25
#define NEGINF (-CUDART_INF_F)

#define ROW_BYTES   516
#define GROUP_ROWS  4
#define GROUP_BYTES 2064                     // 516*4, 16B multiple
#define FIRST_ROW   24                       // 516*24 is 16B aligned
#define NGROUPS     58
#define NSLOTS      3
#define WPB         4

// Strictly monotone float -> uint32 key (order-preserving bijection)
static __device__ __forceinline__ unsigned fkey(float f) {
    unsigned u = __float_as_uint(f);
    return u ^ ((unsigned)((int)u >> 31) | 0x80000000u);
}

static __device__ __forceinline__ uint32_t smem_u32(const void* p) {
    uint32_t a;
    asm("{ .reg .u64 t; cvta.to.shared.u64 t, %1; cvt.u32.u64 %0, t; }" : "=r"(a) : "l"(p));
    return a;
}
static __device__ __forceinline__ void mbar_init(uint32_t mbar, uint32_t cnt) {
    asm volatile("mbarrier.init.shared.b64 [%0], %1;" :: "r"(mbar), "r"(cnt) : "memory");
}
static __device__ __forceinline__ void mbar_expect_tx(uint32_t mbar, uint32_t bytes) {
    asm volatile("mbarrier.arrive.expect_tx.shared.b64 _, [%0], %1;"
                 :: "r"(mbar), "r"(bytes) : "memory");
}
static __device__ __forceinline__ void bulk_g2s(uint32_t dst, const void* src, uint32_t bytes, uint32_t mbar) {
    asm volatile("cp.async.bulk.shared::cta.global.mbarrier::complete_tx::bytes [%0], [%1], %2, [%3];"
                 :: "r"(dst), "l"(src), "r"(bytes), "r"(mbar) : "memory");
}
static __device__ __forceinline__ void mbar_wait(uint32_t mbar, uint32_t parity) {
    uint32_t done;
    asm volatile("{\n\t.reg .pred p;\n\t"
                 "mbarrier.try_wait.parity.acquire.cta.shared::cta.b64 p, [%1], %2;\n\t"
                 "selp.b32 %0, 1, 0, p;\n\t}"
                 : "=r"(done) : "r"(mbar), "r"(parity) : "memory");
    if (!done) {
        asm volatile("{\n\t.reg .pred P1;\n\t"
                     "W_%=:\n\t"
                     "mbarrier.try_wait.parity.acquire.cta.shared::cta.b64 P1, [%0], %1, 0x989680;\n\t"
                     "@P1 bra.uni D_%=;\n\t"
                     "bra.uni W_%=;\n\t"
                     "D_%=:\n\t}"
                     :: "r"(mbar), "r"(parity) : "memory");
    }
}

__global__ void __launch_bounds__(128, 7)
greedy_matching_kernel(const float* __restrict__ x, float* __restrict__ out) {
    __shared__ __align__(128) unsigned char sbuf[WPB][NSLOTS][GROUP_BYTES];
    __shared__ __align__(8)   unsigned long long smbar[WPB][NSLOTS];

    const int wib  = threadIdx.x >> 5;
    const int lane = threadIdx.x & 31;
    const int warp = blockIdx.x * WPB + wib;

    const float* __restrict__ base = x + (size_t)warp * (VSZ * NU);
    float* __restrict__ pi_out = out + BATCH + (size_t)warp * VSZ;

    const uint32_t sb  = smem_u32(&sbuf[wib][0][0]);
    const uint32_t mbb = smem_u32(&smbar[wib][0]);

    if (lane == 0) {
        mbar_init(mbb + 0, 1); mbar_init(mbb + 8, 1); mbar_init(mbb + 16, 1);
        asm volatile("fence.proxy.async.shared::cta;" ::: "memory");
#pragma unroll
        for (int s = 0; s < NSLOTS; ++s) {
            mbar_expect_tx(mbb + 8u * s, GROUP_BYTES);
            bulk_g2s(sb + s * GROUP_BYTES,
                     base + (size_t)(FIRST_ROW + GROUP_ROWS * s) * NU,
                     GROUP_BYTES, mbb + 8u * s);
        }
    }
    __syncwarp();

    // Skip phase: t = 0..23 (t = 24 is emitted with group 0's vector store)
    if (lane < FIRST_ROW) pi_out[lane] = 0.0f;

    // Availability bias: 0 = available, -inf = matched.
    // Lane l owns j = l, l+32, l+64, l+96; j = 128 real only on lane 0.
    float b0 = 0.f, b1 = 0.f, b2 = 0.f, b3 = 0.f;
    float b4 = (lane == 0) ? 0.f : NEGINF;
    const float z0 = (lane == 0) ? 0.f : 1.f;  // forces skip weight to 0 on lane 0
    float size = 0.f;

#define LOADW(P, rp) \
    float P##0 = (rp)[lane];      float P##1 = (rp)[lane + 32]; \
    float P##2 = (rp)[lane + 64]; float P##3 = (rp)[lane + 96]; \
    float P##4 = (rp)[128];

    // One greedy step. Lane-local arg index built from the max tree (strict '>'
    // keeps the smallest j on in-lane ties); REDUX.min over winner composites
    // gives the globally smallest j among max-key holders (== argmax first-index).
#define STEP(P, POUT) do {                                                     \
        float f0 = fmaf(P##0, z0, b0);                                         \
        float f1 = P##1 + b1;                                                  \
        float f2 = P##2 + b2;                                                  \
        float f3 = P##3 + b3;                                                  \
        float f4 = P##4 + b4;                                                  \
        float m01 = fmaxf(f0, f1);                                             \
        float m23 = fmaxf(f2, f3);                                             \
        float m03 = fmaxf(m01, m23);                                           \
        float lm  = fmaxf(m03, f4);                                            \
        int j01 = (f1 > f0)  ? lane + 32 : lane;                               \
        int j23 = (f3 > f2)  ? lane + 96 : lane + 64;                          \
        int jlo = (m23 > m01) ? j23 : j01;                                     \
        int li  = (f4 > m03) ? 128 : jlo;                                      \
        unsigned mk = fkey(lm);                                                \
        unsigned gk = __reduce_max_sync(0xFFFFFFFFu, mk);                      \
        unsigned cand = (mk == gk) ? (unsigned)li : 0xFFFFFFFFu;               \
        int s = (int)__reduce_min_sync(0xFFFFFFFFu, cand);                     \
        /* winner's lm == selected weight; owner lane of s is s&31 */          \
        size += __shfl_sync(0xFFFFFFFFu, lm, s & 31);                          \
        int d = s - lane;                                                      \
        if (d == 0 && s != 0) b0 = NEGINF;                                     \
        if (d == 32)  b1 = NEGINF;                                             \
        if (d == 64)  b2 = NEGINF;                                             \
        if (d == 96)  b3 = NEGINF;                                             \
        if (d == 128) b4 = NEGINF;  /* only lane 0 sees d==128 */              \
        POUT = __int2float_rn(s);                                              \
    } while (0)

    int stage = 0, phase = 0;
    float p0, p1, p2, p3;

    // Group 0: rows 24..27. Row 24 is still in the skip phase (sel 0, no state).
    {
        mbar_wait(mbb + 0, 0);
        const char* sp = (const char*)&sbuf[wib][0][0];
        LOADW(B, (const float*)(sp + 1 * ROW_BYTES));
        LOADW(C, (const float*)(sp + 2 * ROW_BYTES));
        LOADW(D, (const float*)(sp + 3 * ROW_BYTES));
        p0 = 0.0f;
        STEP(B, p1);
        STEP(C, p2);
        STEP(D, p3);
        if (lane == 0) {
            *(float4*)(pi_out + FIRST_ROW) = make_float4(p0, p1, p2, p3);
            mbar_expect_tx(mbb + 0, GROUP_BYTES);
            bulk_g2s(sb + 0,
                     base + (size_t)(FIRST_ROW + GROUP_ROWS * NSLOTS) * NU,
                     GROUP_BYTES, mbb + 0);
        }
        stage = 1;
    }

#pragma unroll 1
    for (int g = 1; g < NGROUPS; ++g) {
        mbar_wait(mbb + 8u * stage, phase);
        const char* sp = (const char*)&sbuf[wib][stage][0];
        // Hoist all 20 weight loads: LDS latency fully off the serial chain.
        LOADW(A, (const float*)(sp + 0 * ROW_BYTES));
        LOADW(B, (const float*)(sp + 1 * ROW_BYTES));
        LOADW(C, (const float*)(sp + 2 * ROW_BYTES));
        LOADW(D, (const float*)(sp + 3 * ROW_BYTES));
        STEP(A, p0);
        STEP(B, p1);
        STEP(C, p2);
        STEP(D, p3);
        const int t0 = FIRST_ROW + GROUP_ROWS * g;
        if (lane == 0) {
            *(float4*)(pi_out + t0) = make_float4(p0, p1, p2, p3);
            if (g + NSLOTS < NGROUPS) {
                // Safe: STEP(D)'s REDUX converged the warp, so every lane has
                // consumed this slot's data before the refill is issued.
                mbar_expect_tx(mbb + 8u * stage, GROUP_BYTES);
                bulk_g2s(sb + stage * GROUP_BYTES,
                         base + (size_t)(t0 + GROUP_ROWS * NSLOTS) * NU,
                         GROUP_BYTES, mbb + 8u * stage);
            }
        }
        if (++stage == NSLOTS) { stage = 0; phase ^= 1; }
    }

    if (lane == 0) out[warp] = -size;
}

extern "C" void kernel_launch(void* const* d_in, const int* in_sizes, int n_in,
                              void* d_out, int out_size) {
    const float* x = (const float*)d_in[0];
    float* out = (float*)d_out;
    greedy_matching_kernel<<<BATCH / WPB, 128>>>(x, out);
}